// round 4
// baseline (speedup 1.0000x reference)
#include <cuda_runtime.h>
#include <cstdint>

#define FULLMASK 0xffffffffu

constexpr int Bb = 8;
constexpr int Tt = 2048;
constexpr int Dd = 1024;
constexpr int Ww = 64;

// scratch: q_local * w2_w, precomputed by GEMM kernel (rows t>=64 only used)
__device__ float g_qlw[(size_t)Bb * Tt * Dd];

// ---------------------------------------------------------------------------
// helpers
// ---------------------------------------------------------------------------
__device__ __forceinline__ uint32_t smem_u32(const void* p) {
    uint32_t a;
    asm("{ .reg .u64 t; cvta.to.shared.u64 t, %1; cvt.u32.u64 %0, t; }"
        : "=r"(a) : "l"(p));
    return a;
}
__device__ __forceinline__ uint32_t mapa_u32(uint32_t a, uint32_t r) {
    uint32_t o;
    asm("mapa.shared::cluster.u32 %0, %1, %2;" : "=r"(o) : "r"(a), "r"(r));
    return o;
}
__device__ __forceinline__ void st_cluster_f32(uint32_t a, float v) {
    asm volatile("st.shared::cluster.b32 [%0], %1;"
                 :: "r"(a), "r"(__float_as_uint(v)) : "memory");
}
__device__ __forceinline__ void cluster_sync_() {
    asm volatile("barrier.cluster.arrive.aligned;" ::: "memory");
    asm volatile("barrier.cluster.wait.aligned;" ::: "memory");
}
__device__ __forceinline__ void mbar_init(uint32_t a, uint32_t cnt) {
    asm volatile("mbarrier.init.shared.b64 [%0], %1;" :: "r"(a), "r"(cnt) : "memory");
}
// remote arrive with release.cluster: orders this thread's prior cluster stores
__device__ __forceinline__ void mbar_arrive_rank(uint32_t la, uint32_t r) {
    asm volatile(
        "{ .reg .b32 ra;\n"
        "  mapa.shared::cluster.u32 ra, %0, %1;\n"
        "  mbarrier.arrive.release.cluster.shared::cluster.b64 _, [ra]; }"
        :: "r"(la), "r"(r) : "memory");
}
// local wait with acquire.cluster: observes remote ranks' released stores
__device__ __forceinline__ void mbar_wait_cluster(uint32_t addr, uint32_t parity) {
    asm volatile(
        "{ .reg .pred p;\n"
        "WL_%=:\n"
        "  mbarrier.try_wait.parity.acquire.cluster.shared::cta.b64 p, [%0], %1, 0x989680;\n"
        "  @p bra.uni WD_%=;\n"
        "  bra.uni WL_%=;\n"
        "WD_%=: }"
        :: "r"(addr), "r"(parity) : "memory");
}
// packed fp32x2 FMA (FFMA2) and pack/unpack
__device__ __forceinline__ void ffma2(unsigned long long& d,
                                      unsigned long long a, unsigned long long b) {
    asm("fma.rn.f32x2 %0, %1, %2, %0;" : "+l"(d) : "l"(a), "l"(b));
}
__device__ __forceinline__ unsigned long long pack2(float lo, float hi) {
    unsigned long long r;
    asm("mov.b64 %0, {%1, %2};" : "=l"(r) : "f"(lo), "f"(hi));
    return r;
}
__device__ __forceinline__ void unpack2(unsigned long long v, float& lo, float& hi) {
    asm("mov.b64 {%0, %1}, %2;" : "=f"(lo), "=f"(hi) : "l"(v));
}

// ---------------------------------------------------------------------------
// Kernel 1: qlw[b,t,:] = (feature[b,t,:] @ wq_w + wq_b) * w2_w   for t >= 64
// 64x64 tile, BK=16, 256 threads, 4x4 microtile, fp32 via packed FFMA2
// ---------------------------------------------------------------------------
__global__ __launch_bounds__(256) void gemm_qlw(
    const float* __restrict__ feat,
    const float* __restrict__ wq,
    const float* __restrict__ wqb,
    const float* __restrict__ w2w)
{
    __shared__ float As[16][68];   // [k][m], stride 68 keeps float4 alignment
    __shared__ float Bs[16][64];   // [k][n]

    const int tid = threadIdx.x;
    const int m0 = blockIdx.y * 64;          // 15872 rows total = 248 tiles
    const int n0 = blockIdx.x * 64;
    const int bb = m0 / 1984;                // 1984 % 64 == 0 -> tile within batch
    const int t0 = Ww + (m0 % 1984);
    const float* Abase = feat + ((size_t)bb * Tt + t0) * Dd;
    float* Obase = g_qlw + ((size_t)bb * Tt + t0) * Dd;

    const int tx = tid & 15, ty = tid >> 4;
    const int ar = tid >> 2, ak = (tid & 3) * 4;
    const int br = tid >> 4, bn = (tid & 15) * 4;

    unsigned long long acc2[4][2] = {};   // [i][jpair] packed fp32x2

    for (int kt = 0; kt < 64; ++kt) {
        float4 a4 = *(const float4*)(Abase + (size_t)ar * Dd + kt * 16 + ak);
        float4 b4 = *(const float4*)(wq + (size_t)(kt * 16 + br) * Dd + n0 + bn);
        __syncthreads();   // previous tile's compute done before overwrite
        As[ak + 0][ar] = a4.x;
        As[ak + 1][ar] = a4.y;
        As[ak + 2][ar] = a4.z;
        As[ak + 3][ar] = a4.w;
        *(float4*)&Bs[br][bn] = b4;
        __syncthreads();
#pragma unroll
        for (int k = 0; k < 16; ++k) {
            float4 av = *(const float4*)&As[k][ty * 4];
            float4 bv = *(const float4*)&Bs[k][tx * 4];
            unsigned long long b01 = pack2(bv.x, bv.y);
            unsigned long long b23 = pack2(bv.z, bv.w);
            float a[4] = {av.x, av.y, av.z, av.w};
#pragma unroll
            for (int i = 0; i < 4; i++) {
                unsigned long long aa = pack2(a[i], a[i]);
                ffma2(acc2[i][0], aa, b01);
                ffma2(acc2[i][1], aa, b23);
            }
        }
    }

    float4 bias4 = *(const float4*)(wqb + n0 + tx * 4);
    float4 sc4   = *(const float4*)(w2w + n0 + tx * 4);
#pragma unroll
    for (int i = 0; i < 4; i++) {
        float a0, a1, a2, a3;
        unpack2(acc2[i][0], a0, a1);
        unpack2(acc2[i][1], a2, a3);
        float4 ov;
        ov.x = (a0 + bias4.x) * sc4.x;
        ov.y = (a1 + bias4.y) * sc4.y;
        ov.z = (a2 + bias4.z) * sc4.z;
        ov.w = (a3 + bias4.w) * sc4.w;
        *(float4*)(Obase + (size_t)(ty * 4 + i) * Dd + n0 + tx * 4) = ov;
    }
}

// ---------------------------------------------------------------------------
// Kernel 2: sequential softmax-window scan.
// 1 cluster (4 CTAs) per batch. CTA rank owns d in [rank*256, rank*256+256).
// 1024 threads = 256 d-columns x 4 slot-groups; each thread holds 16 ring
// slots of its column in registers. Softmax over 64 slots + implicit zero row.
// Cross-CTA score exchange: st.shared::cluster + mbarrier release/acquire
// (no cluster.sync in the loop -> no 490cyc barrier, no per-step L1D flush).
// ---------------------------------------------------------------------------
__global__ void __cluster_dims__(4, 1, 1) __launch_bounds__(1024, 1)
scan_kernel(const float* __restrict__ feat, float* __restrict__ out)
{
    __shared__ float s_part[64][9];        // per-(slot, warp-in-group) partials
    __shared__ float s_psc[2][4][64];      // [parity][source rank][slot]
    __shared__ __align__(16) float s_alpha[64];
    __shared__ float s_vtmp[4][256];       // per-group v partials
    __shared__ __align__(8) unsigned long long s_mbar[2];

    const int tid  = threadIdx.x;
    const int lane = tid & 31;
    const int wg   = (tid >> 5) & 7;       // warp index within slot-group
    const int h    = tid >> 8;             // slot-group 0..3 (slots h*16..h*16+15)
    const int dl   = tid & 255;            // local d
    const uint32_t rank  = blockIdx.x & 3;
    const uint32_t batch = blockIdx.x >> 2;
    const int dg = (int)rank * 256 + dl;   // global d

    const float* qbase = g_qlw + (size_t)batch * Tt * Dd;
    const float* fbase = feat + (size_t)batch * Tt * Dd;
    float* obase = out + (size_t)batch * Tt * Dd;

    const uint32_t mb0 = smem_u32(&s_mbar[0]);
    const uint32_t mb1 = smem_u32(&s_mbar[1]);
    if (tid == 0) {
        mbar_init(mb0, 256);   // 64 threads x 4 ranks arrive per phase
        mbar_init(mb1, 256);
    }
    // make mbarrier init visible cluster-wide before any remote arrives
    cluster_sync_();

    // init ring buffer: slot p holds feature row p (p = h*16 + k)
    float buf[16];
#pragma unroll
    for (int k = 0; k < 16; k++)
        buf[k] = fbase[(size_t)(h * 16 + k) * Dd + dg];

    float qt = qbase[(size_t)Ww * Dd + dg];
    int par = 0;

    for (int t = Ww; t < Tt; ++t, par ^= 1) {
        const int tn = (t + 1 < Tt) ? (t + 1) : (Tt - 1);
        const float qn = qbase[(size_t)tn * Dd + dg];   // prefetch next step

        // ---- score partials over this thread's 16 slots ----
        float arr[16];
#pragma unroll
        for (int k = 0; k < 16; k++) arr[k] = buf[k] * qt;

        // fold the two half-warps (both halves end up identical)
#pragma unroll
        for (int k = 0; k < 16; k++)
            arr[k] += __shfl_xor_sync(FULLMASK, arr[k], 16);

        // transpose-reduce: 16 values over 16 lanes -> value j lands on lane j
        const int l4 = lane & 15;
#pragma unroll
        for (int m = 8; m >= 1; m >>= 1) {
#pragma unroll
            for (int k = 0; k < m; k++) {
                float send = (l4 & m) ? arr[k] : arr[k + m];
                float recv = __shfl_xor_sync(FULLMASK, send, m);
                float keep = (l4 & m) ? arr[k + m] : arr[k];
                arr[k] = keep + recv;
            }
        }
        if (lane < 16) s_part[h * 16 + lane][wg] = arr[0];
        __syncthreads();                                       // B1

        // ---- combine warps, broadcast CTA partial scores to all 4 ranks,
        //      then release-arrive on every rank's barrier ----
        const uint32_t mbp = par ? mb1 : mb0;
        if (tid < 64) {
            float s = 0.f;
#pragma unroll
            for (int w = 0; w < 8; w++) s += s_part[tid][w];
            uint32_t la = smem_u32(&s_psc[par][rank][tid]);
#pragma unroll
            for (uint32_t r = 0; r < 4; r++)
                st_cluster_f32(mapa_u32(la, r), s);
#pragma unroll
            for (uint32_t r = 0; r < 4; r++)
                mbar_arrive_rank(mbp, r);
        }

        // ---- softmax over 64 scores + zero row (logit 0 -> +1 in the sum).
        //      Logits are provably O(1) here, so no max subtraction needed. ----
        if (tid < 32) {
            mbar_wait_cluster(mbp, ((uint32_t)(t - Ww) >> 1) & 1);
            float s0 = 0.f, s1 = 0.f;
#pragma unroll
            for (int c = 0; c < 4; c++) {
                s0 += s_psc[par][c][tid];
                s1 += s_psc[par][c][tid + 32];
            }
            float e0 = __expf(s0), e1 = __expf(s1);
            float sm = e0 + e1;
#pragma unroll
            for (int m = 16; m >= 1; m >>= 1)
                sm += __shfl_xor_sync(FULLMASK, sm, m);
            float inv = 1.f / (sm + 1.f);   // zero-row term exp(0)
            s_alpha[tid]      = e0 * inv;
            s_alpha[tid + 32] = e1 * inv;
        }
        __syncthreads();                                       // B3

        // ---- v partial over this thread's slots ----
        float4 a0 = *(const float4*)&s_alpha[h * 16 + 0];
        float4 a1 = *(const float4*)&s_alpha[h * 16 + 4];
        float4 a2 = *(const float4*)&s_alpha[h * 16 + 8];
        float4 a3 = *(const float4*)&s_alpha[h * 16 + 12];
        float al[16] = {a0.x, a0.y, a0.z, a0.w, a1.x, a1.y, a1.z, a1.w,
                        a2.x, a2.y, a2.z, a2.w, a3.x, a3.y, a3.z, a3.w};
        float pv = 0.f;
#pragma unroll
        for (int k = 0; k < 16; k++) pv += buf[k] * al[k];
        s_vtmp[h][dl] = pv;
        __syncthreads();                                       // B4

        // ---- owner group assembles v[d], stores it, inserts into ring ----
        const int slot = t & 63;
        if ((slot >> 4) == h) {
            float v = s_vtmp[0][dl] + s_vtmp[1][dl] + s_vtmp[2][dl] + s_vtmp[3][dl];
            obase[(size_t)t * Dd + dg] = v;
            const int si = slot & 15;
#pragma unroll
            for (int k = 0; k < 16; k++)
                if (k == si) buf[k] = v;
        }
        qt = qn;
    }

    // all inbound traffic is consumed before each CTA reaches here; trailing
    // cluster sync keeps CTA lifetimes overlapped for DSMEM safety
    cluster_sync_();
}

// ---------------------------------------------------------------------------
// Kernel 3: y = tanh(v)*f + f; LayerNorm over D; in-place on out.
// Rows t < 64 use feature directly (scan never wrote them).
// ---------------------------------------------------------------------------
__device__ __forceinline__ float block_reduce_sum(float v, float* red, float* bc) {
    const int lane = threadIdx.x & 31, w = threadIdx.x >> 5;
#pragma unroll
    for (int m = 16; m >= 1; m >>= 1) v += __shfl_xor_sync(FULLMASK, v, m);
    if (lane == 0) red[w] = v;
    __syncthreads();
    if (threadIdx.x < 8) {
        float x = red[threadIdx.x];
#pragma unroll
        for (int m = 4; m >= 1; m >>= 1) x += __shfl_xor_sync(0xffu, x, m);
        if (threadIdx.x == 0) *bc = x;
    }
    __syncthreads();
    float r = *bc;
    __syncthreads();   // safe reuse of red/bc on the next call
    return r;
}

__global__ __launch_bounds__(256) void epilogue(
    const float* __restrict__ feat,
    const float* __restrict__ lng,
    const float* __restrict__ lnb,
    float* __restrict__ out)
{
    __shared__ float red[8];
    __shared__ float bc;

    const int row = blockIdx.x;
    const int t = row & (Tt - 1);
    const float* f = feat + (size_t)row * Dd;
    float* o = out + (size_t)row * Dd;
    const int tid = threadIdx.x;

    float4 f4 = *(const float4*)(f + tid * 4);
    float4 v4 = (t < Ww) ? f4 : *(const float4*)(o + tid * 4);

    float y[4];
    y[0] = tanhf(v4.x) * f4.x + f4.x;
    y[1] = tanhf(v4.y) * f4.y + f4.y;
    y[2] = tanhf(v4.z) * f4.z + f4.z;
    y[3] = tanhf(v4.w) * f4.w + f4.w;

    float total = block_reduce_sum(y[0] + y[1] + y[2] + y[3], red, &bc);
    float mu = total * (1.f / 1024.f);

    float c0 = y[0] - mu, c1 = y[1] - mu, c2 = y[2] - mu, c3 = y[3] - mu;
    float sq = block_reduce_sum(c0 * c0 + c1 * c1 + c2 * c2 + c3 * c3, red, &bc);
    float rs = rsqrtf(sq * (1.f / 1024.f) + 1e-5f);

    float4 g4 = *(const float4*)(lng + tid * 4);
    float4 b4 = *(const float4*)(lnb + tid * 4);
    float4 ov;
    ov.x = c0 * rs * g4.x + b4.x;
    ov.y = c1 * rs * g4.y + b4.y;
    ov.z = c2 * rs * g4.z + b4.z;
    ov.w = c3 * rs * g4.w + b4.w;
    *(float4*)(o + tid * 4) = ov;
}

// ---------------------------------------------------------------------------
extern "C" void kernel_launch(void* const* d_in, const int* in_sizes, int n_in,
                              void* d_out, int out_size)
{
    const float* feature = (const float*)d_in[0];
    const float* wq_w    = (const float*)d_in[1];
    const float* wq_b    = (const float*)d_in[2];
    const float* w2_w    = (const float*)d_in[3];
    // d_in[4] (w2_b) is unused: a constant added to every softmax logit,
    // including the zero row, cancels exactly.
    const float* ln_g    = (const float*)d_in[5];
    const float* ln_b    = (const float*)d_in[6];
    float* out = (float*)d_out;

    gemm_qlw<<<dim3(16, 248), 256>>>(feature, wq_w, wq_b, w2_w);
    scan_kernel<<<Bb * 4, 1024>>>(feature, out);
    epilogue<<<Bb * Tt, 256>>>(feature, ln_g, ln_b, out);
}

// round 5
// speedup vs baseline: 1.4780x; 1.4780x over previous
#include <cuda_runtime.h>
#include <cstdint>

#define FULLMASK 0xffffffffu

constexpr int Bb = 8;
constexpr int Tt = 2048;
constexpr int Dd = 1024;
constexpr int Ww = 64;
constexpr int NCHUNK = 31;            // (2048-64)/64 chunks of 64 rows per batch
constexpr int NTILES_N = 4;           // 4 n-tiles of 256 per chunk

// scratch: q_local * w2_w (rows t>=64 used), produced by GEMM blocks
__device__ float g_qlw[(size_t)Bb * Tt * Dd];
// readiness counters: g_cnt[c*8+b] counts completed n-tiles (target 4)
__device__ int g_cnt[NCHUNK * Bb];

// ---------------------------------------------------------------------------
// helpers
// ---------------------------------------------------------------------------
__device__ __forceinline__ uint32_t smem_u32(const void* p) {
    uint32_t a;
    asm("{ .reg .u64 t; cvta.to.shared.u64 t, %1; cvt.u32.u64 %0, t; }"
        : "=r"(a) : "l"(p));
    return a;
}
__device__ __forceinline__ uint32_t mapa_u32(uint32_t a, uint32_t r) {
    uint32_t o;
    asm("mapa.shared::cluster.u32 %0, %1, %2;" : "=r"(o) : "r"(a), "r"(r));
    return o;
}
__device__ __forceinline__ void st_cluster_f32(uint32_t a, float v) {
    asm volatile("st.shared::cluster.b32 [%0], %1;"
                 :: "r"(a), "r"(__float_as_uint(v)) : "memory");
}
__device__ __forceinline__ void cluster_sync_() {
    asm volatile("barrier.cluster.arrive.aligned;" ::: "memory");
    asm volatile("barrier.cluster.wait.aligned;" ::: "memory");
}
__device__ __forceinline__ int ld_acquire_gpu(const int* p) {
    int v;
    asm volatile("ld.acquire.gpu.b32 %0, [%1];" : "=r"(v) : "l"(p) : "memory");
    return v;
}

// ---------------------------------------------------------------------------
// init: zero readiness counters (runs before fused kernel each launch)
// ---------------------------------------------------------------------------
__global__ void init_flags() {
    if (threadIdx.x < NCHUNK * Bb) g_cnt[threadIdx.x] = 0;
}

// ---------------------------------------------------------------------------
// GEMM body: one block computes qlw[b, t0..t0+64, n0..n0+256)
// 64x256 tile, BK=16, 1024 threads, 4x4 microtile, plain fp32 FFMA.
// ---------------------------------------------------------------------------
__device__ void gemm_body(
    int gid,
    const float* __restrict__ feat,
    const float* __restrict__ wq,
    const float* __restrict__ wqb,
    const float* __restrict__ w2w,
    float (*As)[69], float (*Bs)[256])
{
    const int c = gid >> 5;                 // chunk 0..30
    const int r5 = gid & 31;
    const int b = r5 >> 2;                  // batch
    const int n = r5 & 3;                   // n-tile
    const int t0 = Ww + c * 64;
    const int n0 = n * 256;

    const float* Abase = feat + ((size_t)b * Tt + t0) * Dd;
    float* Obase = g_qlw + ((size_t)b * Tt + t0) * Dd;

    const int tid = threadIdx.x;
    const int tx = tid & 63, ty = tid >> 6;         // micro: m=ty*4.., n=tx*4..
    const int ar = tid >> 4, ak = tid & 15;         // A load: 64x16, 1/thread
    const int br = tid >> 6, bc = (tid & 63) * 4;   // B load: 16x256, float4

    float acc[4][4] = {};

    for (int kt = 0; kt < 64; ++kt) {
        float a1 = Abase[(size_t)ar * Dd + kt * 16 + ak];
        float4 b4 = *(const float4*)(wq + (size_t)(kt * 16 + br) * Dd + n0 + bc);
        __syncthreads();
        As[ak][ar] = a1;
        *(float4*)&Bs[br][bc] = b4;
        __syncthreads();
#pragma unroll
        for (int k = 0; k < 16; ++k) {
            float4 bv = *(const float4*)&Bs[k][tx * 4];
            float bl[4] = {bv.x, bv.y, bv.z, bv.w};
#pragma unroll
            for (int i = 0; i < 4; i++) {
                float av = As[k][ty * 4 + i];
#pragma unroll
                for (int j = 0; j < 4; j++)
                    acc[i][j] += av * bl[j];
            }
        }
    }

    float4 bias4 = *(const float4*)(wqb + n0 + tx * 4);
    float4 sc4   = *(const float4*)(w2w + n0 + tx * 4);
#pragma unroll
    for (int i = 0; i < 4; i++) {
        float4 ov;
        ov.x = (acc[i][0] + bias4.x) * sc4.x;
        ov.y = (acc[i][1] + bias4.y) * sc4.y;
        ov.z = (acc[i][2] + bias4.z) * sc4.z;
        ov.w = (acc[i][3] + bias4.w) * sc4.w;
        *(float4*)(Obase + (size_t)(ty * 4 + i) * Dd + n0 + tx * 4) = ov;
    }

    // publish: all stores -> fence -> barrier -> one atomic bump
    __threadfence();
    __syncthreads();
    if (tid == 0) atomicAdd(&g_cnt[c * Bb + b], 1);
}

// ---------------------------------------------------------------------------
// Scan body: sequential softmax-window scan (R2 protocol: cluster.sync).
// 1 cluster (4 CTAs) per batch; CTA rank owns d in [rank*256, rank*256+256).
// Ring of 64 slots in registers (16/thread). Softmax over 64 slots + zero row
// (no max subtraction: logits are O(1) here; w2_b cancels in softmax).
// Gated on per-chunk readiness of g_qlw produced by concurrent GEMM blocks.
// ---------------------------------------------------------------------------
__device__ void scan_body(const float* __restrict__ feat, float* __restrict__ out)
{
    __shared__ float s_part[64][9];        // per-(slot, warp-in-group) partials
    __shared__ float s_psc[2][4][64];      // [parity][source rank][slot]
    __shared__ __align__(16) float s_alpha[64];
    __shared__ float s_vtmp[4][256];       // per-group v partials

    const int tid  = threadIdx.x;
    const int lane = tid & 31;
    const int wg   = (tid >> 5) & 7;       // warp index within slot-group
    const int h    = tid >> 8;             // slot-group 0..3
    const int dl   = tid & 255;            // local d
    const uint32_t rank  = blockIdx.x & 3;
    const uint32_t batch = blockIdx.x >> 2;
    const int dg = (int)rank * 256 + dl;   // global d

    const float* qbase = g_qlw + (size_t)batch * Tt * Dd;
    const float* fbase = feat + (size_t)batch * Tt * Dd;
    float* obase = out + (size_t)batch * Tt * Dd;

    // init ring buffer: slot p holds feature row p (p = h*16 + k)
    float buf[16];
#pragma unroll
    for (int k = 0; k < 16; k++)
        buf[k] = fbase[(size_t)(h * 16 + k) * Dd + dg];

    // wait for chunk 0 of this batch, then load first q row
    if (tid == 0) while (ld_acquire_gpu(&g_cnt[batch]) < NTILES_N) {}
    __syncthreads();
    float qt = qbase[(size_t)Ww * Dd + dg];
    int par = 0;

    for (int t = Ww; t < Tt; ++t, par ^= 1) {
        const int tn = (t + 1 < Tt) ? (t + 1) : (Tt - 1);
        // gate the prefetch when row tn enters a new chunk
        if (((tn - Ww) & 63) == 0 && tn > Ww) {
            const int c = (tn - Ww) >> 6;
            if (tid == 0)
                while (ld_acquire_gpu(&g_cnt[c * Bb + (int)batch]) < NTILES_N) {}
            __syncthreads();
        }
        const float qn = qbase[(size_t)tn * Dd + dg];   // prefetch next step

        // ---- score partials over this thread's 16 slots ----
        float arr[16];
#pragma unroll
        for (int k = 0; k < 16; k++) arr[k] = buf[k] * qt;

        // fold the two half-warps (both halves end up identical)
#pragma unroll
        for (int k = 0; k < 16; k++)
            arr[k] += __shfl_xor_sync(FULLMASK, arr[k], 16);

        // transpose-reduce: 16 values over 16 lanes -> value j lands on lane j
        const int l4 = lane & 15;
#pragma unroll
        for (int m = 8; m >= 1; m >>= 1) {
#pragma unroll
            for (int k = 0; k < m; k++) {
                float send = (l4 & m) ? arr[k] : arr[k + m];
                float recv = __shfl_xor_sync(FULLMASK, send, m);
                float keep = (l4 & m) ? arr[k + m] : arr[k];
                arr[k] = keep + recv;
            }
        }
        if (lane < 16) s_part[h * 16 + lane][wg] = arr[0];
        __syncthreads();

        // ---- combine warps, broadcast CTA partial scores to all 4 ranks ----
        if (tid < 64) {
            float s = 0.f;
#pragma unroll
            for (int w = 0; w < 8; w++) s += s_part[tid][w];
            uint32_t la = smem_u32(&s_psc[par][rank][tid]);
#pragma unroll
            for (uint32_t r = 0; r < 4; r++)
                st_cluster_f32(mapa_u32(la, r), s);
        }
        // arrive has release semantics: orders the st.shared::cluster stores
        cluster_sync_();

        // ---- softmax over 64 scores + zero row (exp(0)=1), warp 0 only ----
        if (tid < 32) {
            float s0 = 0.f, s1 = 0.f;
#pragma unroll
            for (int c = 0; c < 4; c++) {
                s0 += s_psc[par][c][tid];
                s1 += s_psc[par][c][tid + 32];
            }
            float e0 = __expf(s0), e1 = __expf(s1);
            float sm = e0 + e1;
#pragma unroll
            for (int m = 16; m >= 1; m >>= 1)
                sm += __shfl_xor_sync(FULLMASK, sm, m);
            float inv = 1.f / (sm + 1.f);
            s_alpha[tid]      = e0 * inv;
            s_alpha[tid + 32] = e1 * inv;
        }
        __syncthreads();

        // ---- v partial over this thread's slots ----
        float4 a0 = *(const float4*)&s_alpha[h * 16 + 0];
        float4 a1 = *(const float4*)&s_alpha[h * 16 + 4];
        float4 a2 = *(const float4*)&s_alpha[h * 16 + 8];
        float4 a3 = *(const float4*)&s_alpha[h * 16 + 12];
        float al[16] = {a0.x, a0.y, a0.z, a0.w, a1.x, a1.y, a1.z, a1.w,
                        a2.x, a2.y, a2.z, a2.w, a3.x, a3.y, a3.z, a3.w};
        float pv = 0.f;
#pragma unroll
        for (int k = 0; k < 16; k++) pv += buf[k] * al[k];
        s_vtmp[h][dl] = pv;
        __syncthreads();

        // ---- owner group assembles v[d], stores it, inserts into ring ----
        const int slot = t & 63;
        if ((slot >> 4) == h) {
            float v = s_vtmp[0][dl] + s_vtmp[1][dl] + s_vtmp[2][dl] + s_vtmp[3][dl];
            obase[(size_t)t * Dd + dg] = v;
            const int si = slot & 15;
#pragma unroll
            for (int k = 0; k < 16; k++)
                if (k == si) buf[k] = v;
        }
        qt = qn;
    }
    cluster_sync_();   // keep CTA lifetimes overlapped for DSMEM safety
}

// ---------------------------------------------------------------------------
// Fused kernel: blocks 0..31 = 8 scan clusters; blocks 32..1023 = GEMM tiles
// ordered chunk-major so each batch's chunk c is ready well before the scan
// consumes it. Scan blocks are first -> wave-1 residency.
// ---------------------------------------------------------------------------
__global__ void __cluster_dims__(4, 1, 1) __launch_bounds__(1024, 1)
fused_kernel(const float* __restrict__ feat,
             const float* __restrict__ wq,
             const float* __restrict__ wqb,
             const float* __restrict__ w2w,
             float* __restrict__ out)
{
    __shared__ float As[16][69];
    __shared__ float Bs[16][256];

    if (blockIdx.x < 32) {
        scan_body(feat, out);
    } else {
        gemm_body((int)blockIdx.x - 32, feat, wq, wqb, w2w, As, Bs);
    }
}

// ---------------------------------------------------------------------------
// Epilogue: y = tanh(v)*f + f; LayerNorm over D; in-place on out.
// Rows t < 64 use feature directly (scan never wrote them).
// ---------------------------------------------------------------------------
__device__ __forceinline__ float block_reduce_sum(float v, float* red, float* bc) {
    const int lane = threadIdx.x & 31, w = threadIdx.x >> 5;
#pragma unroll
    for (int m = 16; m >= 1; m >>= 1) v += __shfl_xor_sync(FULLMASK, v, m);
    if (lane == 0) red[w] = v;
    __syncthreads();
    if (threadIdx.x < 8) {
        float x = red[threadIdx.x];
#pragma unroll
        for (int m = 4; m >= 1; m >>= 1) x += __shfl_xor_sync(0xffu, x, m);
        if (threadIdx.x == 0) *bc = x;
    }
    __syncthreads();
    float r = *bc;
    __syncthreads();   // safe reuse of red/bc on the next call
    return r;
}

__global__ __launch_bounds__(256) void epilogue(
    const float* __restrict__ feat,
    const float* __restrict__ lng,
    const float* __restrict__ lnb,
    float* __restrict__ out)
{
    __shared__ float red[8];
    __shared__ float bc;

    const int row = blockIdx.x;
    const int t = row & (Tt - 1);
    const float* f = feat + (size_t)row * Dd;
    float* o = out + (size_t)row * Dd;
    const int tid = threadIdx.x;

    float4 f4 = *(const float4*)(f + tid * 4);
    float4 v4 = (t < Ww) ? f4 : *(const float4*)(o + tid * 4);

    float y[4];
    y[0] = tanhf(v4.x) * f4.x + f4.x;
    y[1] = tanhf(v4.y) * f4.y + f4.y;
    y[2] = tanhf(v4.z) * f4.z + f4.z;
    y[3] = tanhf(v4.w) * f4.w + f4.w;

    float total = block_reduce_sum(y[0] + y[1] + y[2] + y[3], red, &bc);
    float mu = total * (1.f / 1024.f);

    float c0 = y[0] - mu, c1 = y[1] - mu, c2 = y[2] - mu, c3 = y[3] - mu;
    float sq = block_reduce_sum(c0 * c0 + c1 * c1 + c2 * c2 + c3 * c3, red, &bc);
    float rs = rsqrtf(sq * (1.f / 1024.f) + 1e-5f);

    float4 g4 = *(const float4*)(lng + tid * 4);
    float4 b4 = *(const float4*)(lnb + tid * 4);
    float4 ov;
    ov.x = c0 * rs * g4.x + b4.x;
    ov.y = c1 * rs * g4.y + b4.y;
    ov.z = c2 * rs * g4.z + b4.z;
    ov.w = c3 * rs * g4.w + b4.w;
    *(float4*)(o + tid * 4) = ov;
}

// ---------------------------------------------------------------------------
extern "C" void kernel_launch(void* const* d_in, const int* in_sizes, int n_in,
                              void* d_out, int out_size)
{
    const float* feature = (const float*)d_in[0];
    const float* wq_w    = (const float*)d_in[1];
    const float* wq_b    = (const float*)d_in[2];
    const float* w2_w    = (const float*)d_in[3];
    // d_in[4] (w2_b) unused: constant logit offset cancels in softmax.
    const float* ln_g    = (const float*)d_in[5];
    const float* ln_b    = (const float*)d_in[6];
    float* out = (float*)d_out;

    init_flags<<<1, 256>>>();
    fused_kernel<<<32 + NCHUNK * Bb * NTILES_N, 1024>>>(feature, wq_w, wq_b, w2_w, out);
    epilogue<<<Bb * Tt, 256>>>(feature, ln_g, ln_b, out);
}